// round 5
// baseline (speedup 1.0000x reference)
#include <cuda_runtime.h>

#define FULL 0xffffffffu

static constexpr int NMAX = 262144;   // 4*16*4096 nodes

// Scratch (allocation-free: device globals)
__device__ float         g_S[(size_t)NMAX * 64];
__device__ float         g_s0[NMAX];
__device__ unsigned char g_mask[NMAX];

// ---------------------------------------------------------------------------
// butterfly reduction of two values across the warp
__device__ __forceinline__ void warp_reduce2(float& s, float& q) {
    #pragma unroll
    for (int o = 16; o > 0; o >>= 1) {
        s += __shfl_xor_sync(FULL, s, o);
        q += __shfl_xor_sync(FULL, q, o);
    }
}

// packed f32x2 FMA: acc += {ax,ay} * {bx,by}
__device__ __forceinline__ void ffma2(float2& acc, float ax, float ay,
                                      float bx, float by) {
    float2 a = make_float2(ax, ay);
    float2 b = make_float2(bx, by);
    asm("fma.rn.f32x2 %0, %1, %2, %0;"
        : "+l"(reinterpret_cast<unsigned long long&>(acc))
        : "l"(reinterpret_cast<unsigned long long&>(a)),
          "l"(reinterpret_cast<unsigned long long&>(b)));
}

// ---------------------------------------------------------------------------
__global__ void __launch_bounds__(256) zero_kernel(int N) {
    const int stride = gridDim.x * blockDim.x;
    const int i = blockIdx.x * blockDim.x + threadIdx.x;
    const float4 z = make_float4(0.f, 0.f, 0.f, 0.f);
    const size_t total4 = (size_t)N * 16;
    for (size_t j = i; j < total4; j += stride)
        reinterpret_cast<float4*>(g_S)[j] = z;
    for (int j = i; j < N; j += stride) {
        g_s0[j] = 0.f;
        g_mask[j] = 0;
    }
}

// ---------------------------------------------------------------------------
// Edge kernel: warp processes 8 edges per iteration, 3 CTAs/SM.
// ---------------------------------------------------------------------------
__global__ void __launch_bounds__(256, 3) edge_kernel(
    const float* __restrict__ gf,
    const float* __restrict__ pos,
    const int*   __restrict__ edge,
    const float* __restrict__ wgt,
    const float* __restrict__ W1,
    const float* __restrict__ b1,
    const float* __restrict__ W2,
    const float* __restrict__ b2,
    const float* __restrict__ gdg,
    const float* __restrict__ gdb,
    int E)
{
    __shared__ float sW2t[64 * 68];     // W2t[c][k] = W2[k][c], pitch 68
    __shared__ float sht[8 * 8 * 64];   // h staging: [warp][edge][k]

    for (int i = threadIdx.x; i < 64 * 64; i += 256) {
        int k = i >> 6, c = i & 63;
        sW2t[c * 68 + k] = W2[i];
    }
    __syncthreads();

    const int lane = threadIdx.x & 31;
    const int warp = threadIdx.x >> 5;
    const int lhi  = lane + 32;

    // per-lane constants in registers (channels lane, lane+32)
    const float w1aLo = __ldg(W1 + lane),     w1bLo = __ldg(W1 + 64 + lane);
    const float w1aHi = __ldg(W1 + lhi),      w1bHi = __ldg(W1 + 64 + lhi);
    const float b1Lo  = __ldg(b1 + lane),     b1Hi  = __ldg(b1 + lhi);
    const float b2Lo  = __ldg(b2 + lane),     b2Hi  = __ldg(b2 + lhi);
    const float gLo   = __ldg(gdg + lane),    gHi   = __ldg(gdg + lhi);
    const float btLo  = __ldg(gdb + lane),    btHi  = __ldg(gdb + lhi);

    float* hme = sht + warp * 512;
    const float4* wrLo = reinterpret_cast<const float4*>(sW2t + lane * 68);
    const float4* wrHi = reinterpret_cast<const float4*>(sW2t + lhi * 68);

    const int nw = gridDim.x * 8;
    for (int e0 = (blockIdx.x * 8 + warp) * 8; e0 < E; e0 += nw * 8) {
        int pre = 0, suc = 0;
        float pd0 = 0.f, pd1 = 0.f, w = 0.f;
        if (lane < 8) {
            const int ei = min(e0 + lane, E - 1);
            const int4 ed = __ldg(reinterpret_cast<const int4*>(edge) + ei);
            pre = (ed.x * 16 + ed.y) * 4096 + ed.z;
            suc = pre - ed.z + 4096 + ed.w;
            const float2 P0 = __ldg(reinterpret_cast<const float2*>(pos) + ed.y * 4096 + ed.z);
            const float2 P1 = __ldg(reinterpret_cast<const float2*>(pos) + (ed.y + 1) * 4096 + ed.w);
            pd0 = P1.x - P0.x;
            pd1 = P1.y - P0.y;
            w = __ldg(wgt + ei);
        }
        __syncwarp();

        // hoist gathers: issue all 16 LDG now, consume after the GEMV
        float vLo[8], vHi[8];
        #pragma unroll
        for (int e = 0; e < 8; e++) {
            const int preE = __shfl_sync(FULL, pre, e);
            vLo[e] = __ldg(gf + (size_t)preE * 64 + lane);
            vHi[e] = __ldg(gf + (size_t)preE * 64 + lhi);
        }

        // compute + stage h for 8 edges (natural k order)
        #pragma unroll
        for (int e = 0; e < 8; e++) {
            const float p0 = __shfl_sync(FULL, pd0, e);
            const float p1 = __shfl_sync(FULL, pd1, e);
            const float za = fmaf(p1, w1bLo, fmaf(p0, w1aLo, b1Lo));
            const float zb = fmaf(p1, w1bHi, fmaf(p0, w1aHi, b1Hi));
            hme[e * 64 + lane] = za > 0.f ? za : 0.01f * za;
            hme[e * 64 + lhi]  = zb > 0.f ? zb : 0.01f * zb;
        }
        __syncwarp();

        float2 aLo[8], aHi[8];
        #pragma unroll
        for (int e = 0; e < 8; e++) {
            aLo[e] = make_float2(b2Lo, 0.f);
            aHi[e] = make_float2(b2Hi, 0.f);
        }
        #pragma unroll
        for (int kq = 0; kq < 16; kq++) {
            const float4 wl = wrLo[kq];
            const float4 wh = wrHi[kq];
            #pragma unroll
            for (int e = 0; e < 8; e++) {
                const float4 h4 = *reinterpret_cast<const float4*>(hme + e * 64 + kq * 4);
                ffma2(aLo[e], h4.x, h4.y, wl.x, wl.y);
                ffma2(aLo[e], h4.z, h4.w, wl.z, wl.w);
                ffma2(aHi[e], h4.x, h4.y, wh.x, wh.y);
                ffma2(aHi[e], h4.z, h4.w, wh.z, wh.w);
            }
        }

        #pragma unroll
        for (int e = 0; e < 8; e++) {
            const float yLo = aLo[e].x + aLo[e].y;
            const float yHi = aHi[e].x + aHi[e].y;
            float s = yLo + yHi;
            float q = fmaf(yLo, yLo, yHi * yHi);
            warp_reduce2(s, q);
            const float mean = s * 0.015625f;
            const float var  = fmaf(q, 0.015625f, -mean * mean);
            const float rs   = rsqrtf(var + 1e-5f);
            const float dLo = fmaf((yLo - mean) * rs, gLo, btLo);
            const float dHi = fmaf((yHi - mean) * rs, gHi, btHi);

            const int   sucE = __shfl_sync(FULL, suc, e);
            const float wE   = __shfl_sync(FULL, w, e);

            const float ox = wE * (vLo[e] + dLo);
            const float oy = wE * (vHi[e] + dHi);

            // regroup for vectorized reductions
            const float a1 = __shfl_down_sync(FULL, ox, 1);
            const float a2 = __shfl_down_sync(FULL, ox, 2);
            const float a3 = __shfl_down_sync(FULL, ox, 3);
            const float u2 = __shfl_up_sync(FULL, oy, 2);
            const float u1 = __shfl_up_sync(FULL, oy, 1);
            const float d1 = __shfl_down_sync(FULL, oy, 1);

            if (e0 + e < E) {
                if ((lane & 3) == 0) {
                    float* adr = g_S + (size_t)sucE * 64 + lane;   // channels lane..lane+3
                    asm volatile("red.global.add.v4.f32 [%0], {%1,%2,%3,%4};"
                                 :: "l"(adr), "f"(ox), "f"(a1), "f"(a2), "f"(a3) : "memory");
                }
                if ((lane & 3) == 2) {
                    float* adr = g_S + (size_t)sucE * 64 + 30 + lane; // channels 32+(lane-2)..
                    asm volatile("red.global.add.v4.f32 [%0], {%1,%2,%3,%4};"
                                 :: "l"(adr), "f"(u2), "f"(u1), "f"(oy), "f"(d1) : "memory");
                }
                if (lane == 0) {
                    atomicAdd(g_s0 + sucE, wE);
                    g_mask[sucE] = 1;
                }
            }
        }
    }
}

// ---------------------------------------------------------------------------
// Node kernel: warp processes 8 nodes per iteration, 3 CTAs/SM.
// cp values go straight to smem in the phase-1 epilogue (no register arrays).
// ---------------------------------------------------------------------------
__global__ void __launch_bounds__(256, 3) node_kernel(
    const float* __restrict__ gf,
    const float* __restrict__ Wa,
    const float* __restrict__ ba,
    const float* __restrict__ gng,
    const float* __restrict__ gnb,
    const float* __restrict__ Wf,
    const float* __restrict__ bf,
    const float* __restrict__ gfg,
    const float* __restrict__ gfb,
    float* __restrict__ out,
    int N)
{
    extern __shared__ float sm[];
    float* sWa  = sm;                    // 64*68  = 4352 floats
    float* sWf  = sm + 4352;             // 64*132 = 8448 floats
    float* sAct = sm + 4352 + 8448;      // 8 warps * 8 nodes * 128 = 8192 floats

    for (int i = threadIdx.x; i < 64 * 64; i += 256) {
        int k = i >> 6, c = i & 63;
        sWa[c * 68 + k] = Wa[i];
    }
    for (int i = threadIdx.x; i < 128 * 64; i += 256) {
        int k = i >> 6, c = i & 63;
        sWf[c * 132 + k] = Wf[i];
    }
    __syncthreads();

    const int lane = threadIdx.x & 31;
    const int warp = threadIdx.x >> 5;
    const int lhi  = lane + 32;

    const float baLo = __ldg(ba + lane),  baHi = __ldg(ba + lhi);
    const float gnLo = __ldg(gng + lane), gnHi = __ldg(gng + lhi);
    const float gbLo = __ldg(gnb + lane), gbHi = __ldg(gnb + lhi);
    const float bfLo = __ldg(bf + lane),  bfHi = __ldg(bf + lhi);
    const float fgLo = __ldg(gfg + lane), fgHi = __ldg(gfg + lhi);
    const float fbLo = __ldg(gfb + lane), fbHi = __ldg(gfb + lhi);

    float* actw = sAct + warp * 1024;
    const float4* waLo = reinterpret_cast<const float4*>(sWa + lane * 68);
    const float4* waHi = reinterpret_cast<const float4*>(sWa + lhi * 68);
    const float4* wfLo = reinterpret_cast<const float4*>(sWf + lane * 132);
    const float4* wfHi = reinterpret_cast<const float4*>(sWf + lhi * 132);

    const int nw = gridDim.x * 8;
    for (int n0 = (blockIdx.x * 8 + warp) * 8; n0 < N; n0 += nw * 8) {
        const unsigned msk = __ballot_sync(FULL, (lane < 8) && g_mask[n0 + lane]);
        if (msk == 0) {   // all 8 nodes untouched: copy through
            const float4* src = reinterpret_cast<const float4*>(gf + (size_t)n0 * 64);
            float4* dst = reinterpret_cast<float4*>(out + (size_t)n0 * 64);
            #pragma unroll
            for (int j = 0; j < 4; j++)
                dst[j * 32 + lane] = src[j * 32 + lane];
            continue;
        }
        const float s0v = (lane < 8) ? g_s0[n0 + lane] : 0.f;

        __syncwarp();
        float2 gfv[8];
        #pragma unroll
        for (int e = 0; e < 8; e++) {
            const float2 sv = *(reinterpret_cast<const float2*>(g_S) + (size_t)(n0 + e) * 32 + lane);
            reinterpret_cast<float2*>(actw + e * 128)[lane] = sv;   // S into kk 0..63
            gfv[e] = __ldg(reinterpret_cast<const float2*>(gf) + (size_t)(n0 + e) * 32 + lane);
        }
        __syncwarp();

        // phase 1: copy_pre = S @ Wa + s0*ba
        float2 aLo[8], aHi[8];
        #pragma unroll
        for (int e = 0; e < 8; e++) {
            const float s0e = __shfl_sync(FULL, s0v, e);
            aLo[e] = make_float2(s0e * baLo, 0.f);
            aHi[e] = make_float2(s0e * baHi, 0.f);
        }
        #pragma unroll
        for (int kq = 0; kq < 16; kq++) {
            const float4 wl = waLo[kq];
            const float4 wh = waHi[kq];
            #pragma unroll
            for (int e = 0; e < 8; e++) {
                const float4 h4 = *reinterpret_cast<const float4*>(actw + e * 128 + kq * 4);
                ffma2(aLo[e], h4.x, h4.y, wl.x, wl.y);
                ffma2(aLo[e], h4.z, h4.w, wl.z, wl.w);
                ffma2(aHi[e], h4.x, h4.y, wh.x, wh.y);
                ffma2(aHi[e], h4.z, h4.w, wh.z, wh.w);
            }
        }
        // GN(gn_n) -> write copy straight into smem region kk 64..127
        #pragma unroll
        for (int e = 0; e < 8; e++) {
            const float yLo = aLo[e].x + aLo[e].y;
            const float yHi = aHi[e].x + aHi[e].y;
            float s = yLo + yHi;
            float q = fmaf(yLo, yLo, yHi * yHi);
            warp_reduce2(s, q);
            const float mean = s * 0.015625f;
            const float var  = fmaf(q, 0.015625f, -mean * mean);
            const float rs   = rsqrtf(var + 1e-5f);
            actw[e * 128 + 64 + lane] = fmaf((yLo - mean) * rs, gnLo, gbLo);
            actw[e * 128 + 96 + lane] = fmaf((yHi - mean) * rs, gnHi, gbHi);
        }

        __syncwarp();   // all lanes done reading S from actw
        #pragma unroll
        for (int e = 0; e < 8; e++)
            reinterpret_cast<float2*>(actw + e * 128)[lane] = gfv[e];  // kk 0..63 = gf
        __syncwarp();

        // phase 2: fused = [gf, copy] @ Wf + bf
        #pragma unroll
        for (int e = 0; e < 8; e++) {
            aLo[e] = make_float2(bfLo, 0.f);
            aHi[e] = make_float2(bfHi, 0.f);
        }
        #pragma unroll
        for (int kq = 0; kq < 32; kq++) {
            const float4 wl = wfLo[kq];
            const float4 wh = wfHi[kq];
            #pragma unroll
            for (int e = 0; e < 8; e++) {
                const float4 h4 = *reinterpret_cast<const float4*>(actw + e * 128 + kq * 4);
                ffma2(aLo[e], h4.x, h4.y, wl.x, wl.y);
                ffma2(aLo[e], h4.z, h4.w, wl.z, wl.w);
                ffma2(aHi[e], h4.x, h4.y, wh.x, wh.y);
                ffma2(aHi[e], h4.z, h4.w, wh.z, wh.w);
            }
        }
        #pragma unroll
        for (int e = 0; e < 8; e++) {
            const float yLo = aLo[e].x + aLo[e].y;
            const float yHi = aHi[e].x + aHi[e].y;
            float s = yLo + yHi;
            float q = fmaf(yLo, yLo, yHi * yHi);
            warp_reduce2(s, q);
            const float mean = s * 0.015625f;
            const float var  = fmaf(q, 0.015625f, -mean * mean);
            const float rs   = rsqrtf(var + 1e-5f);
            float fLo = fmaf((yLo - mean) * rs, fgLo, fbLo);
            float fHi = fmaf((yHi - mean) * rs, fgHi, fbHi);
            fLo = fLo > 0.f ? fLo : 0.01f * fLo;
            fHi = fHi > 0.f ? fHi : 0.01f * fHi;
            if ((msk >> e) & 1) {
                out[(size_t)(n0 + e) * 64 + lane] = fLo;
                out[(size_t)(n0 + e) * 64 + lhi]  = fHi;
            } else {
                reinterpret_cast<float2*>(out)[(size_t)(n0 + e) * 32 + lane] = gfv[e];
            }
        }
    }
}

// ---------------------------------------------------------------------------
extern "C" void kernel_launch(void* const* d_in, const int* in_sizes, int n_in,
                              void* d_out, int out_size)
{
    const float* gf  = (const float*)d_in[0];
    const float* pos = (const float*)d_in[1];
    const int*   edg = (const int*)  d_in[2];
    const float* wgt = (const float*)d_in[3];
    const float* W1  = (const float*)d_in[4];
    const float* b1  = (const float*)d_in[5];
    const float* W2  = (const float*)d_in[6];
    const float* b2  = (const float*)d_in[7];
    const float* gdg = (const float*)d_in[8];
    const float* gdb = (const float*)d_in[9];
    const float* Wa  = (const float*)d_in[10];
    const float* ba  = (const float*)d_in[11];
    const float* gng = (const float*)d_in[12];
    const float* gnb = (const float*)d_in[13];
    const float* Wf  = (const float*)d_in[14];
    const float* bf  = (const float*)d_in[15];
    const float* gfg = (const float*)d_in[16];
    const float* gfb = (const float*)d_in[17];
    float* out = (float*)d_out;

    const int E = in_sizes[3];
    const int N = in_sizes[0] / 64;

    static const size_t node_smem = (4352 + 8448 + 8192) * sizeof(float);
    cudaFuncSetAttribute(node_kernel, cudaFuncAttributeMaxDynamicSharedMemorySize,
                         (int)node_smem);

    zero_kernel<<<2368, 256>>>(N);
    edge_kernel<<<444, 256>>>(gf, pos, edg, wgt, W1, b1, W2, b2, gdg, gdb, E);
    node_kernel<<<444, 256, node_smem>>>(gf, Wa, ba, gng, gnb, Wf, bf, gfg, gfb, out, N);
}

// round 6
// speedup vs baseline: 1.0649x; 1.0649x over previous
#include <cuda_runtime.h>

#define FULL 0xffffffffu

static constexpr int NMAX = 262144;   // 4*16*4096 nodes

// Scratch (allocation-free: device globals)
__device__ float         g_S[(size_t)NMAX * 64];
__device__ float         g_s0[NMAX];
__device__ unsigned char g_mask[NMAX];

// packed f32x2 FMA: acc += {ax,ay} * {bx,by}
__device__ __forceinline__ void ffma2(float2& acc, float ax, float ay,
                                      float bx, float by) {
    float2 a = make_float2(ax, ay);
    float2 b = make_float2(bx, by);
    asm("fma.rn.f32x2 %0, %1, %2, %0;"
        : "+l"(reinterpret_cast<unsigned long long&>(acc))
        : "l"(reinterpret_cast<unsigned long long&>(a)),
          "l"(reinterpret_cast<unsigned long long&>(b)));
}

// ---------------------------------------------------------------------------
__global__ void __launch_bounds__(256) zero_kernel(int N) {
    const int stride = gridDim.x * blockDim.x;
    const int i = blockIdx.x * blockDim.x + threadIdx.x;
    const float4 z = make_float4(0.f, 0.f, 0.f, 0.f);
    const size_t total4 = (size_t)N * 16;
    for (size_t j = i; j < total4; j += stride)
        reinterpret_cast<float4*>(g_S)[j] = z;
    for (int j = i; j < N; j += stride) {
        g_s0[j] = 0.f;
        g_mask[j] = 0;
    }
}

// ---------------------------------------------------------------------------
// Edge kernel: warp processes 8 edges per iteration; GN butterflies batched
// across all 8 edges for ILP (16 independent shfl chains per level).
// ---------------------------------------------------------------------------
__global__ void __launch_bounds__(256, 2) edge_kernel(
    const float* __restrict__ gf,
    const float* __restrict__ pos,
    const int*   __restrict__ edge,
    const float* __restrict__ wgt,
    const float* __restrict__ W1,
    const float* __restrict__ b1,
    const float* __restrict__ W2,
    const float* __restrict__ b2,
    const float* __restrict__ gdg,
    const float* __restrict__ gdb,
    int E)
{
    __shared__ float sW2t[64 * 68];     // W2t[c][k] = W2[k][c], pitch 68
    __shared__ float sht[8 * 8 * 64];   // h staging: [warp][edge][k]

    for (int i = threadIdx.x; i < 64 * 64; i += 256) {
        int k = i >> 6, c = i & 63;
        sW2t[c * 68 + k] = W2[i];
    }
    __syncthreads();

    const int lane = threadIdx.x & 31;
    const int warp = threadIdx.x >> 5;
    const int lhi  = lane + 32;

    // per-lane constants in registers (channels lane, lane+32)
    const float w1aLo = __ldg(W1 + lane),     w1bLo = __ldg(W1 + 64 + lane);
    const float w1aHi = __ldg(W1 + lhi),      w1bHi = __ldg(W1 + 64 + lhi);
    const float b1Lo  = __ldg(b1 + lane),     b1Hi  = __ldg(b1 + lhi);
    const float b2Lo  = __ldg(b2 + lane),     b2Hi  = __ldg(b2 + lhi);
    const float gLo   = __ldg(gdg + lane),    gHi   = __ldg(gdg + lhi);
    const float btLo  = __ldg(gdb + lane),    btHi  = __ldg(gdb + lhi);

    float* hme = sht + warp * 512;
    const float4* wrLo = reinterpret_cast<const float4*>(sW2t + lane * 68);
    const float4* wrHi = reinterpret_cast<const float4*>(sW2t + lhi * 68);

    const int nw = gridDim.x * 8;
    for (int e0 = (blockIdx.x * 8 + warp) * 8; e0 < E; e0 += nw * 8) {
        int pre = 0, suc = 0;
        float pd0 = 0.f, pd1 = 0.f, w = 0.f;
        if (lane < 8) {
            const int ei = min(e0 + lane, E - 1);
            const int4 ed = __ldg(reinterpret_cast<const int4*>(edge) + ei);
            pre = (ed.x * 16 + ed.y) * 4096 + ed.z;
            suc = pre - ed.z + 4096 + ed.w;
            const float2 P0 = __ldg(reinterpret_cast<const float2*>(pos) + ed.y * 4096 + ed.z);
            const float2 P1 = __ldg(reinterpret_cast<const float2*>(pos) + (ed.y + 1) * 4096 + ed.w);
            pd0 = P1.x - P0.x;
            pd1 = P1.y - P0.y;
            w = __ldg(wgt + ei);
        }
        __syncwarp();

        // hoist gathers: issue all 16 LDG now, consume after the GEMV
        float vLo[8], vHi[8];
        #pragma unroll
        for (int e = 0; e < 8; e++) {
            const int preE = __shfl_sync(FULL, pre, e);
            vLo[e] = __ldg(gf + (size_t)preE * 64 + lane);
            vHi[e] = __ldg(gf + (size_t)preE * 64 + lhi);
        }

        // compute + stage h for 8 edges (natural k order)
        #pragma unroll
        for (int e = 0; e < 8; e++) {
            const float p0 = __shfl_sync(FULL, pd0, e);
            const float p1 = __shfl_sync(FULL, pd1, e);
            const float za = fmaf(p1, w1bLo, fmaf(p0, w1aLo, b1Lo));
            const float zb = fmaf(p1, w1bHi, fmaf(p0, w1aHi, b1Hi));
            hme[e * 64 + lane] = za > 0.f ? za : 0.01f * za;
            hme[e * 64 + lhi]  = zb > 0.f ? zb : 0.01f * zb;
        }
        __syncwarp();

        float2 aLo[8], aHi[8];
        #pragma unroll
        for (int e = 0; e < 8; e++) {
            aLo[e] = make_float2(b2Lo, 0.f);
            aHi[e] = make_float2(b2Hi, 0.f);
        }
        #pragma unroll
        for (int kq = 0; kq < 16; kq++) {
            const float4 wl = wrLo[kq];
            const float4 wh = wrHi[kq];
            #pragma unroll
            for (int e = 0; e < 8; e++) {
                const float4 h4 = *reinterpret_cast<const float4*>(hme + e * 64 + kq * 4);
                ffma2(aLo[e], h4.x, h4.y, wl.x, wl.y);
                ffma2(aLo[e], h4.z, h4.w, wl.z, wl.w);
                ffma2(aHi[e], h4.x, h4.y, wh.x, wh.y);
                ffma2(aHi[e], h4.z, h4.w, wh.z, wh.w);
            }
        }

        // ---- batched GN reductions: 16 independent chains per level ----
        float yLo[8], yHi[8], sA[8], qA[8];
        #pragma unroll
        for (int e = 0; e < 8; e++) {
            yLo[e] = aLo[e].x + aLo[e].y;
            yHi[e] = aHi[e].x + aHi[e].y;
            sA[e]  = yLo[e] + yHi[e];
            qA[e]  = fmaf(yLo[e], yLo[e], yHi[e] * yHi[e]);
        }
        #pragma unroll
        for (int o = 16; o > 0; o >>= 1) {
            #pragma unroll
            for (int e = 0; e < 8; e++)
                sA[e] += __shfl_xor_sync(FULL, sA[e], o);
            #pragma unroll
            for (int e = 0; e < 8; e++)
                qA[e] += __shfl_xor_sync(FULL, qA[e], o);
        }

        #pragma unroll
        for (int e = 0; e < 8; e++) {
            const float mean = sA[e] * 0.015625f;
            const float var  = fmaf(qA[e], 0.015625f, -mean * mean);
            const float rs   = rsqrtf(var + 1e-5f);
            const float dLo  = fmaf((yLo[e] - mean) * rs, gLo, btLo);
            const float dHi  = fmaf((yHi[e] - mean) * rs, gHi, btHi);

            const int   sucE = __shfl_sync(FULL, suc, e);
            const float wE   = __shfl_sync(FULL, w, e);

            const float ox = wE * (vLo[e] + dLo);
            const float oy = wE * (vHi[e] + dHi);

            // regroup for vectorized reductions (6 independent shfls)
            const float a1 = __shfl_down_sync(FULL, ox, 1);
            const float a2 = __shfl_down_sync(FULL, ox, 2);
            const float a3 = __shfl_down_sync(FULL, ox, 3);
            const float u2 = __shfl_up_sync(FULL, oy, 2);
            const float u1 = __shfl_up_sync(FULL, oy, 1);
            const float d1 = __shfl_down_sync(FULL, oy, 1);

            if (e0 + e < E) {
                if ((lane & 3) == 0) {
                    float* adr = g_S + (size_t)sucE * 64 + lane;   // channels lane..lane+3
                    asm volatile("red.global.add.v4.f32 [%0], {%1,%2,%3,%4};"
                                 :: "l"(adr), "f"(ox), "f"(a1), "f"(a2), "f"(a3) : "memory");
                }
                if ((lane & 3) == 2) {
                    float* adr = g_S + (size_t)sucE * 64 + 30 + lane; // channels 32+(lane-2)..
                    asm volatile("red.global.add.v4.f32 [%0], {%1,%2,%3,%4};"
                                 :: "l"(adr), "f"(u2), "f"(u1), "f"(oy), "f"(d1) : "memory");
                }
                if (lane == 0) {
                    atomicAdd(g_s0 + sucE, wE);
                    g_mask[sucE] = 1;
                }
            }
        }
    }
}

// ---------------------------------------------------------------------------
// Node kernel: warp processes 8 nodes per iteration; batched GN butterflies;
// cp values written straight to smem in the phase-1 epilogue.
// ---------------------------------------------------------------------------
__global__ void __launch_bounds__(256, 2) node_kernel(
    const float* __restrict__ gf,
    const float* __restrict__ Wa,
    const float* __restrict__ ba,
    const float* __restrict__ gng,
    const float* __restrict__ gnb,
    const float* __restrict__ Wf,
    const float* __restrict__ bf,
    const float* __restrict__ gfg,
    const float* __restrict__ gfb,
    float* __restrict__ out,
    int N)
{
    extern __shared__ float sm[];
    float* sWa  = sm;                    // 64*68  = 4352 floats
    float* sWf  = sm + 4352;             // 64*132 = 8448 floats
    float* sAct = sm + 4352 + 8448;      // 8 warps * 8 nodes * 128 = 8192 floats

    for (int i = threadIdx.x; i < 64 * 64; i += 256) {
        int k = i >> 6, c = i & 63;
        sWa[c * 68 + k] = Wa[i];
    }
    for (int i = threadIdx.x; i < 128 * 64; i += 256) {
        int k = i >> 6, c = i & 63;
        sWf[c * 132 + k] = Wf[i];
    }
    __syncthreads();

    const int lane = threadIdx.x & 31;
    const int warp = threadIdx.x >> 5;
    const int lhi  = lane + 32;

    const float baLo = __ldg(ba + lane),  baHi = __ldg(ba + lhi);
    const float gnLo = __ldg(gng + lane), gnHi = __ldg(gng + lhi);
    const float gbLo = __ldg(gnb + lane), gbHi = __ldg(gnb + lhi);
    const float bfLo = __ldg(bf + lane),  bfHi = __ldg(bf + lhi);
    const float fgLo = __ldg(gfg + lane), fgHi = __ldg(gfg + lhi);
    const float fbLo = __ldg(gfb + lane), fbHi = __ldg(gfb + lhi);

    float* actw = sAct + warp * 1024;
    const float4* waLo = reinterpret_cast<const float4*>(sWa + lane * 68);
    const float4* waHi = reinterpret_cast<const float4*>(sWa + lhi * 68);
    const float4* wfLo = reinterpret_cast<const float4*>(sWf + lane * 132);
    const float4* wfHi = reinterpret_cast<const float4*>(sWf + lhi * 132);

    const int nw = gridDim.x * 8;
    for (int n0 = (blockIdx.x * 8 + warp) * 8; n0 < N; n0 += nw * 8) {
        const unsigned msk = __ballot_sync(FULL, (lane < 8) && g_mask[n0 + lane]);
        if (msk == 0) {   // all 8 nodes untouched: copy through
            const float4* src = reinterpret_cast<const float4*>(gf + (size_t)n0 * 64);
            float4* dst = reinterpret_cast<float4*>(out + (size_t)n0 * 64);
            #pragma unroll
            for (int j = 0; j < 4; j++)
                dst[j * 32 + lane] = src[j * 32 + lane];
            continue;
        }
        const float s0v = (lane < 8) ? g_s0[n0 + lane] : 0.f;

        __syncwarp();
        float2 gfv[8];
        #pragma unroll
        for (int e = 0; e < 8; e++) {
            const float2 sv = *(reinterpret_cast<const float2*>(g_S) + (size_t)(n0 + e) * 32 + lane);
            reinterpret_cast<float2*>(actw + e * 128)[lane] = sv;   // S into kk 0..63
            gfv[e] = __ldg(reinterpret_cast<const float2*>(gf) + (size_t)(n0 + e) * 32 + lane);
        }
        __syncwarp();

        // phase 1: copy_pre = S @ Wa + s0*ba
        float2 aLo[8], aHi[8];
        #pragma unroll
        for (int e = 0; e < 8; e++) {
            const float s0e = __shfl_sync(FULL, s0v, e);
            aLo[e] = make_float2(s0e * baLo, 0.f);
            aHi[e] = make_float2(s0e * baHi, 0.f);
        }
        #pragma unroll
        for (int kq = 0; kq < 16; kq++) {
            const float4 wl = waLo[kq];
            const float4 wh = waHi[kq];
            #pragma unroll
            for (int e = 0; e < 8; e++) {
                const float4 h4 = *reinterpret_cast<const float4*>(actw + e * 128 + kq * 4);
                ffma2(aLo[e], h4.x, h4.y, wl.x, wl.y);
                ffma2(aLo[e], h4.z, h4.w, wl.z, wl.w);
                ffma2(aHi[e], h4.x, h4.y, wh.x, wh.y);
                ffma2(aHi[e], h4.z, h4.w, wh.z, wh.w);
            }
        }
        // batched GN(gn_n) -> copy straight into smem region kk 64..127
        {
            float yLo[8], yHi[8], sA[8], qA[8];
            #pragma unroll
            for (int e = 0; e < 8; e++) {
                yLo[e] = aLo[e].x + aLo[e].y;
                yHi[e] = aHi[e].x + aHi[e].y;
                sA[e]  = yLo[e] + yHi[e];
                qA[e]  = fmaf(yLo[e], yLo[e], yHi[e] * yHi[e]);
            }
            #pragma unroll
            for (int o = 16; o > 0; o >>= 1) {
                #pragma unroll
                for (int e = 0; e < 8; e++)
                    sA[e] += __shfl_xor_sync(FULL, sA[e], o);
                #pragma unroll
                for (int e = 0; e < 8; e++)
                    qA[e] += __shfl_xor_sync(FULL, qA[e], o);
            }
            #pragma unroll
            for (int e = 0; e < 8; e++) {
                const float mean = sA[e] * 0.015625f;
                const float var  = fmaf(qA[e], 0.015625f, -mean * mean);
                const float rs   = rsqrtf(var + 1e-5f);
                actw[e * 128 + 64 + lane] = fmaf((yLo[e] - mean) * rs, gnLo, gbLo);
                actw[e * 128 + 96 + lane] = fmaf((yHi[e] - mean) * rs, gnHi, gbHi);
            }
        }

        __syncwarp();   // all lanes done reading S from actw
        #pragma unroll
        for (int e = 0; e < 8; e++)
            reinterpret_cast<float2*>(actw + e * 128)[lane] = gfv[e];  // kk 0..63 = gf
        __syncwarp();

        // phase 2: fused = [gf, copy] @ Wf + bf
        #pragma unroll
        for (int e = 0; e < 8; e++) {
            aLo[e] = make_float2(bfLo, 0.f);
            aHi[e] = make_float2(bfHi, 0.f);
        }
        #pragma unroll
        for (int kq = 0; kq < 32; kq++) {
            const float4 wl = wfLo[kq];
            const float4 wh = wfHi[kq];
            #pragma unroll
            for (int e = 0; e < 8; e++) {
                const float4 h4 = *reinterpret_cast<const float4*>(actw + e * 128 + kq * 4);
                ffma2(aLo[e], h4.x, h4.y, wl.x, wl.y);
                ffma2(aLo[e], h4.z, h4.w, wl.z, wl.w);
                ffma2(aHi[e], h4.x, h4.y, wh.x, wh.y);
                ffma2(aHi[e], h4.z, h4.w, wh.z, wh.w);
            }
        }
        // batched GN(gn_f) + leaky + writeback
        {
            float yLo[8], yHi[8], sA[8], qA[8];
            #pragma unroll
            for (int e = 0; e < 8; e++) {
                yLo[e] = aLo[e].x + aLo[e].y;
                yHi[e] = aHi[e].x + aHi[e].y;
                sA[e]  = yLo[e] + yHi[e];
                qA[e]  = fmaf(yLo[e], yLo[e], yHi[e] * yHi[e]);
            }
            #pragma unroll
            for (int o = 16; o > 0; o >>= 1) {
                #pragma unroll
                for (int e = 0; e < 8; e++)
                    sA[e] += __shfl_xor_sync(FULL, sA[e], o);
                #pragma unroll
                for (int e = 0; e < 8; e++)
                    qA[e] += __shfl_xor_sync(FULL, qA[e], o);
            }
            #pragma unroll
            for (int e = 0; e < 8; e++) {
                const float mean = sA[e] * 0.015625f;
                const float var  = fmaf(qA[e], 0.015625f, -mean * mean);
                const float rs   = rsqrtf(var + 1e-5f);
                float fLo = fmaf((yLo[e] - mean) * rs, fgLo, fbLo);
                float fHi = fmaf((yHi[e] - mean) * rs, fgHi, fbHi);
                fLo = fLo > 0.f ? fLo : 0.01f * fLo;
                fHi = fHi > 0.f ? fHi : 0.01f * fHi;
                if ((msk >> e) & 1) {
                    out[(size_t)(n0 + e) * 64 + lane] = fLo;
                    out[(size_t)(n0 + e) * 64 + lhi]  = fHi;
                } else {
                    reinterpret_cast<float2*>(out)[(size_t)(n0 + e) * 32 + lane] = gfv[e];
                }
            }
        }
    }
}

// ---------------------------------------------------------------------------
extern "C" void kernel_launch(void* const* d_in, const int* in_sizes, int n_in,
                              void* d_out, int out_size)
{
    const float* gf  = (const float*)d_in[0];
    const float* pos = (const float*)d_in[1];
    const int*   edg = (const int*)  d_in[2];
    const float* wgt = (const float*)d_in[3];
    const float* W1  = (const float*)d_in[4];
    const float* b1  = (const float*)d_in[5];
    const float* W2  = (const float*)d_in[6];
    const float* b2  = (const float*)d_in[7];
    const float* gdg = (const float*)d_in[8];
    const float* gdb = (const float*)d_in[9];
    const float* Wa  = (const float*)d_in[10];
    const float* ba  = (const float*)d_in[11];
    const float* gng = (const float*)d_in[12];
    const float* gnb = (const float*)d_in[13];
    const float* Wf  = (const float*)d_in[14];
    const float* bf  = (const float*)d_in[15];
    const float* gfg = (const float*)d_in[16];
    const float* gfb = (const float*)d_in[17];
    float* out = (float*)d_out;

    const int E = in_sizes[3];
    const int N = in_sizes[0] / 64;

    static const size_t node_smem = (4352 + 8448 + 8192) * sizeof(float);
    cudaFuncSetAttribute(node_kernel, cudaFuncAttributeMaxDynamicSharedMemorySize,
                         (int)node_smem);

    zero_kernel<<<2368, 256>>>(N);
    edge_kernel<<<296, 256>>>(gf, pos, edg, wgt, W1, b1, W2, b2, gdg, gdb, E);
    node_kernel<<<296, 256, node_smem>>>(gf, Wa, ba, gng, gnb, Wf, bf, gfg, gfb, out, N);
}

// round 8
// speedup vs baseline: 1.1117x; 1.0439x over previous
#include <cuda_runtime.h>

#define FULL 0xffffffffu

static constexpr int NMAX = 262144;   // 4*16*4096 nodes

// Scratch (allocation-free: device globals)
__device__ float         g_S[(size_t)NMAX * 64];
__device__ float         g_s0[NMAX];
__device__ unsigned char g_mask[NMAX];

// packed f32x2 FMA: acc += {ax,ay} * {bx,by}
__device__ __forceinline__ void ffma2(float2& acc, float ax, float ay,
                                      float bx, float by) {
    float2 a = make_float2(ax, ay);
    float2 b = make_float2(bx, by);
    asm("fma.rn.f32x2 %0, %1, %2, %0;"
        : "+l"(reinterpret_cast<unsigned long long&>(acc))
        : "l"(reinterpret_cast<unsigned long long&>(a)),
          "l"(reinterpret_cast<unsigned long long&>(b)));
}

// ---------------------------------------------------------------------------
__global__ void __launch_bounds__(256) zero_kernel(int N) {
    const int stride = gridDim.x * blockDim.x;
    const int i = blockIdx.x * blockDim.x + threadIdx.x;
    const float4 z = make_float4(0.f, 0.f, 0.f, 0.f);
    const size_t total4 = (size_t)N * 16;
    for (size_t j = i; j < total4; j += stride)
        reinterpret_cast<float4*>(g_S)[j] = z;
    for (int j = i; j < N; j += stride) {
        g_s0[j] = 0.f;
        g_mask[j] = 0;
    }
}

// ---------------------------------------------------------------------------
// Edge kernel: warp processes 8 edges/iter; decode loads software-pipelined
// two iterations deep (edge records) / one deep (pos, wgt).
// ---------------------------------------------------------------------------
__global__ void __launch_bounds__(256, 2) edge_kernel(
    const float* __restrict__ gf,
    const float* __restrict__ pos,
    const int*   __restrict__ edge,
    const float* __restrict__ wgt,
    const float* __restrict__ W1,
    const float* __restrict__ b1,
    const float* __restrict__ W2,
    const float* __restrict__ b2,
    const float* __restrict__ gdg,
    const float* __restrict__ gdb,
    int E)
{
    __shared__ float sW2t[64 * 68];     // W2t[c][k] = W2[k][c], pitch 68
    __shared__ float sht[8 * 8 * 64];   // h staging: [warp][edge][k]

    for (int i = threadIdx.x; i < 64 * 64; i += 256) {
        int k = i >> 6, c = i & 63;
        sW2t[c * 68 + k] = W2[i];
    }
    __syncthreads();

    const int lane = threadIdx.x & 31;
    const int warp = threadIdx.x >> 5;
    const int lhi  = lane + 32;

    const float w1aLo = __ldg(W1 + lane),     w1bLo = __ldg(W1 + 64 + lane);
    const float w1aHi = __ldg(W1 + lhi),      w1bHi = __ldg(W1 + 64 + lhi);
    const float b1Lo  = __ldg(b1 + lane),     b1Hi  = __ldg(b1 + lhi);
    const float b2Lo  = __ldg(b2 + lane),     b2Hi  = __ldg(b2 + lhi);
    const float gLo   = __ldg(gdg + lane),    gHi   = __ldg(gdg + lhi);
    const float btLo  = __ldg(gdb + lane),    btHi  = __ldg(gdb + lhi);

    float* hme = sht + warp * 512;
    const float4* wrLo = reinterpret_cast<const float4*>(sW2t + lane * 68);
    const float4* wrHi = reinterpret_cast<const float4*>(sW2t + lhi * 68);

    const int step = gridDim.x * 64;     // 8 warps * 8 edges
    const int eBeg = (blockIdx.x * 8 + warp) * 8;

    // ---- pipeline prologue ----
    int preC = 0, sucC = 0;
    float pd0C = 0.f, pd1C = 0.f, wC = 0.f;
    int4 edN = make_int4(0, 0, 0, 0);
    if (lane < 8) {
        const int ei = min(eBeg + lane, E - 1);
        const int4 ed = __ldg(reinterpret_cast<const int4*>(edge) + ei);
        preC = (ed.x * 16 + ed.y) * 4096 + ed.z;
        sucC = preC - ed.z + 4096 + ed.w;
        const float2 P0 = __ldg(reinterpret_cast<const float2*>(pos) + ed.y * 4096 + ed.z);
        const float2 P1 = __ldg(reinterpret_cast<const float2*>(pos) + (ed.y + 1) * 4096 + ed.w);
        pd0C = P1.x - P0.x;
        pd1C = P1.y - P0.y;
        wC = __ldg(wgt + ei);
        edN = __ldg(reinterpret_cast<const int4*>(edge) + min(eBeg + step + lane, E - 1));
    }

    for (int e0 = eBeg; e0 < E; e0 += step) {
        // prefetch pos/wgt for iter n+1 (edN arrived last iteration)
        int preN = 0, sucN = 0;
        float pd0N = 0.f, pd1N = 0.f, wN = 0.f;
        if (lane < 8) {
            preN = (edN.x * 16 + edN.y) * 4096 + edN.z;
            sucN = preN - edN.z + 4096 + edN.w;
            const float2 P0 = __ldg(reinterpret_cast<const float2*>(pos) + edN.y * 4096 + edN.z);
            const float2 P1 = __ldg(reinterpret_cast<const float2*>(pos) + (edN.y + 1) * 4096 + edN.w);
            pd0N = P1.x - P0.x;
            pd1N = P1.y - P0.y;
            wN = __ldg(wgt + min(e0 + step + lane, E - 1));
        }

        // gathers for the current iteration (pre ready)
        float vLo[8], vHi[8];
        #pragma unroll
        for (int e = 0; e < 8; e++) {
            const int preE = __shfl_sync(FULL, preC, e);
            vLo[e] = __ldg(gf + (size_t)preE * 64 + lane);
            vHi[e] = __ldg(gf + (size_t)preE * 64 + lhi);
        }

        // prefetch edge records two iterations ahead
        int4 edN2 = make_int4(0, 0, 0, 0);
        if (lane < 8)
            edN2 = __ldg(reinterpret_cast<const int4*>(edge)
                         + min(e0 + 2 * step + lane, E - 1));

        // stage h for 8 edges
        #pragma unroll
        for (int e = 0; e < 8; e++) {
            const float p0 = __shfl_sync(FULL, pd0C, e);
            const float p1 = __shfl_sync(FULL, pd1C, e);
            const float za = fmaf(p1, w1bLo, fmaf(p0, w1aLo, b1Lo));
            const float zb = fmaf(p1, w1bHi, fmaf(p0, w1aHi, b1Hi));
            hme[e * 64 + lane] = za > 0.f ? za : 0.01f * za;
            hme[e * 64 + lhi]  = zb > 0.f ? zb : 0.01f * zb;
        }
        __syncwarp();

        float2 aLo[8], aHi[8];
        #pragma unroll
        for (int e = 0; e < 8; e++) {
            aLo[e] = make_float2(b2Lo, 0.f);
            aHi[e] = make_float2(b2Hi, 0.f);
        }
        #pragma unroll
        for (int kq = 0; kq < 16; kq++) {
            const float4 wl = wrLo[kq];
            const float4 wh = wrHi[kq];
            #pragma unroll
            for (int e = 0; e < 8; e++) {
                const float4 h4 = *reinterpret_cast<const float4*>(hme + e * 64 + kq * 4);
                ffma2(aLo[e], h4.x, h4.y, wl.x, wl.y);
                ffma2(aLo[e], h4.z, h4.w, wl.z, wl.w);
                ffma2(aHi[e], h4.x, h4.y, wh.x, wh.y);
                ffma2(aHi[e], h4.z, h4.w, wh.z, wh.w);
            }
        }
        __syncwarp();   // hme reads done before next iter overwrites

        // batched GN reductions
        float yLo[8], yHi[8], sA[8], qA[8];
        #pragma unroll
        for (int e = 0; e < 8; e++) {
            yLo[e] = aLo[e].x + aLo[e].y;
            yHi[e] = aHi[e].x + aHi[e].y;
            sA[e]  = yLo[e] + yHi[e];
            qA[e]  = fmaf(yLo[e], yLo[e], yHi[e] * yHi[e]);
        }
        #pragma unroll
        for (int o = 16; o > 0; o >>= 1) {
            #pragma unroll
            for (int e = 0; e < 8; e++)
                sA[e] += __shfl_xor_sync(FULL, sA[e], o);
            #pragma unroll
            for (int e = 0; e < 8; e++)
                qA[e] += __shfl_xor_sync(FULL, qA[e], o);
        }

        #pragma unroll
        for (int e = 0; e < 8; e++) {
            const float mean = sA[e] * 0.015625f;
            const float var  = fmaf(qA[e], 0.015625f, -mean * mean);
            const float rs   = rsqrtf(var + 1e-5f);
            const float dLo  = fmaf((yLo[e] - mean) * rs, gLo, btLo);
            const float dHi  = fmaf((yHi[e] - mean) * rs, gHi, btHi);

            const int   sucE = __shfl_sync(FULL, sucC, e);
            const float wE   = __shfl_sync(FULL, wC, e);

            const float ox = wE * (vLo[e] + dLo);
            const float oy = wE * (vHi[e] + dHi);

            const float a1 = __shfl_down_sync(FULL, ox, 1);
            const float a2 = __shfl_down_sync(FULL, ox, 2);
            const float a3 = __shfl_down_sync(FULL, ox, 3);
            const float u2 = __shfl_up_sync(FULL, oy, 2);
            const float u1 = __shfl_up_sync(FULL, oy, 1);
            const float d1 = __shfl_down_sync(FULL, oy, 1);

            if (e0 + e < E) {
                if ((lane & 3) == 0) {
                    float* adr = g_S + (size_t)sucE * 64 + lane;
                    asm volatile("red.global.add.v4.f32 [%0], {%1,%2,%3,%4};"
                                 :: "l"(adr), "f"(ox), "f"(a1), "f"(a2), "f"(a3) : "memory");
                }
                if ((lane & 3) == 2) {
                    float* adr = g_S + (size_t)sucE * 64 + 30 + lane;
                    asm volatile("red.global.add.v4.f32 [%0], {%1,%2,%3,%4};"
                                 :: "l"(adr), "f"(u2), "f"(u1), "f"(oy), "f"(d1) : "memory");
                }
                if (lane == 0) {
                    atomicAdd(g_s0 + sucE, wE);
                    g_mask[sucE] = 1;
                }
            }
        }

        // rotate pipeline registers
        preC = preN; sucC = sucN;
        pd0C = pd0N; pd1C = pd1N; wC = wN;
        edN = edN2;
    }
}

// ---------------------------------------------------------------------------
// Node kernel: warp processes 8 nodes/iter; S/gf/mask/s0 loads software-
// pipelined one iteration deep.
// ---------------------------------------------------------------------------
__global__ void __launch_bounds__(256, 2) node_kernel(
    const float* __restrict__ gf,
    const float* __restrict__ Wa,
    const float* __restrict__ ba,
    const float* __restrict__ gng,
    const float* __restrict__ gnb,
    const float* __restrict__ Wf,
    const float* __restrict__ bf,
    const float* __restrict__ gfg,
    const float* __restrict__ gfb,
    float* __restrict__ out,
    int N)
{
    extern __shared__ float sm[];
    float* sWa  = sm;                    // 64*68  = 4352 floats
    float* sWf  = sm + 4352;             // 64*132 = 8448 floats
    float* sAct = sm + 4352 + 8448;      // 8 warps * 8 nodes * 128 = 8192 floats

    for (int i = threadIdx.x; i < 64 * 64; i += 256) {
        int k = i >> 6, c = i & 63;
        sWa[c * 68 + k] = Wa[i];
    }
    for (int i = threadIdx.x; i < 128 * 64; i += 256) {
        int k = i >> 6, c = i & 63;
        sWf[c * 132 + k] = Wf[i];
    }
    __syncthreads();

    const int lane = threadIdx.x & 31;
    const int warp = threadIdx.x >> 5;
    const int lhi  = lane + 32;

    const float baLo = __ldg(ba + lane),  baHi = __ldg(ba + lhi);
    const float gnLo = __ldg(gng + lane), gnHi = __ldg(gng + lhi);
    const float gbLo = __ldg(gnb + lane), gbHi = __ldg(gnb + lhi);
    const float bfLo = __ldg(bf + lane),  bfHi = __ldg(bf + lhi);
    const float fgLo = __ldg(gfg + lane), fgHi = __ldg(gfg + lhi);
    const float fbLo = __ldg(gfb + lane), fbHi = __ldg(gfb + lhi);

    float* actw = sAct + warp * 1024;
    const float4* waLo = reinterpret_cast<const float4*>(sWa + lane * 68);
    const float4* waHi = reinterpret_cast<const float4*>(sWa + lhi * 68);
    const float4* wfLo = reinterpret_cast<const float4*>(sWf + lane * 132);
    const float4* wfHi = reinterpret_cast<const float4*>(sWf + lhi * 132);

    const int stride = gridDim.x * 64;
    const int nBeg   = (blockIdx.x * 8 + warp) * 8;

    // ---- pipeline prologue: prefetch iteration 0 ----
    unsigned char mC = 0;
    float s0C = 0.f;
    float2 svC[8], gfvC[8];
    if (lane < 8) {
        mC  = g_mask[nBeg + lane];
        s0C = g_s0[nBeg + lane];
    }
    #pragma unroll
    for (int e = 0; e < 8; e++) {
        svC[e]  = *(reinterpret_cast<const float2*>(g_S) + (size_t)(nBeg + e) * 32 + lane);
        gfvC[e] = __ldg(reinterpret_cast<const float2*>(gf) + (size_t)(nBeg + e) * 32 + lane);
    }

    for (int n0 = nBeg; n0 < N; n0 += stride) {
        // ---- prefetch next iteration ----
        const int n1 = n0 + stride;
        unsigned char mN = 0;
        float s0N = 0.f;
        float2 svN[8], gfvN[8];
        if (n1 < N) {
            if (lane < 8) {
                mN  = g_mask[n1 + lane];
                s0N = g_s0[n1 + lane];
            }
            #pragma unroll
            for (int e = 0; e < 8; e++) {
                svN[e]  = *(reinterpret_cast<const float2*>(g_S) + (size_t)(n1 + e) * 32 + lane);
                gfvN[e] = __ldg(reinterpret_cast<const float2*>(gf) + (size_t)(n1 + e) * 32 + lane);
            }
        }

        const unsigned msk = __ballot_sync(FULL, (lane < 8) && mC);
        if (msk == 0) {   // all 8 untouched: write prefetched gf through
            #pragma unroll
            for (int e = 0; e < 8; e++)
                reinterpret_cast<float2*>(out)[(size_t)(n0 + e) * 32 + lane] = gfvC[e];
        } else {
            // stage S into smem
            #pragma unroll
            for (int e = 0; e < 8; e++)
                reinterpret_cast<float2*>(actw + e * 128)[lane] = svC[e];
            __syncwarp();

            // phase 1: copy_pre = S @ Wa + s0*ba
            float2 aLo[8], aHi[8];
            #pragma unroll
            for (int e = 0; e < 8; e++) {
                const float s0e = __shfl_sync(FULL, s0C, e);
                aLo[e] = make_float2(s0e * baLo, 0.f);
                aHi[e] = make_float2(s0e * baHi, 0.f);
            }
            #pragma unroll
            for (int kq = 0; kq < 16; kq++) {
                const float4 wl = waLo[kq];
                const float4 wh = waHi[kq];
                #pragma unroll
                for (int e = 0; e < 8; e++) {
                    const float4 h4 = *reinterpret_cast<const float4*>(actw + e * 128 + kq * 4);
                    ffma2(aLo[e], h4.x, h4.y, wl.x, wl.y);
                    ffma2(aLo[e], h4.z, h4.w, wl.z, wl.w);
                    ffma2(aHi[e], h4.x, h4.y, wh.x, wh.y);
                    ffma2(aHi[e], h4.z, h4.w, wh.z, wh.w);
                }
            }
            {
                float yLo[8], yHi[8], sA[8], qA[8];
                #pragma unroll
                for (int e = 0; e < 8; e++) {
                    yLo[e] = aLo[e].x + aLo[e].y;
                    yHi[e] = aHi[e].x + aHi[e].y;
                    sA[e]  = yLo[e] + yHi[e];
                    qA[e]  = fmaf(yLo[e], yLo[e], yHi[e] * yHi[e]);
                }
                #pragma unroll
                for (int o = 16; o > 0; o >>= 1) {
                    #pragma unroll
                    for (int e = 0; e < 8; e++)
                        sA[e] += __shfl_xor_sync(FULL, sA[e], o);
                    #pragma unroll
                    for (int e = 0; e < 8; e++)
                        qA[e] += __shfl_xor_sync(FULL, qA[e], o);
                }
                #pragma unroll
                for (int e = 0; e < 8; e++) {
                    const float mean = sA[e] * 0.015625f;
                    const float var  = fmaf(qA[e], 0.015625f, -mean * mean);
                    const float rs   = rsqrtf(var + 1e-5f);
                    actw[e * 128 + 64 + lane] = fmaf((yLo[e] - mean) * rs, gnLo, gbLo);
                    actw[e * 128 + 96 + lane] = fmaf((yHi[e] - mean) * rs, gnHi, gbHi);
                }
            }

            __syncwarp();
            #pragma unroll
            for (int e = 0; e < 8; e++)
                reinterpret_cast<float2*>(actw + e * 128)[lane] = gfvC[e];
            __syncwarp();

            // phase 2: fused = [gf, copy] @ Wf + bf
            #pragma unroll
            for (int e = 0; e < 8; e++) {
                aLo[e] = make_float2(bfLo, 0.f);
                aHi[e] = make_float2(bfHi, 0.f);
            }
            #pragma unroll
            for (int kq = 0; kq < 32; kq++) {
                const float4 wl = wfLo[kq];
                const float4 wh = wfHi[kq];
                #pragma unroll
                for (int e = 0; e < 8; e++) {
                    const float4 h4 = *reinterpret_cast<const float4*>(actw + e * 128 + kq * 4);
                    ffma2(aLo[e], h4.x, h4.y, wl.x, wl.y);
                    ffma2(aLo[e], h4.z, h4.w, wl.z, wl.w);
                    ffma2(aHi[e], h4.x, h4.y, wh.x, wh.y);
                    ffma2(aHi[e], h4.z, h4.w, wh.z, wh.w);
                }
            }
            {
                float yLo[8], yHi[8], sA[8], qA[8];
                #pragma unroll
                for (int e = 0; e < 8; e++) {
                    yLo[e] = aLo[e].x + aLo[e].y;
                    yHi[e] = aHi[e].x + aHi[e].y;
                    sA[e]  = yLo[e] + yHi[e];
                    qA[e]  = fmaf(yLo[e], yLo[e], yHi[e] * yHi[e]);
                }
                #pragma unroll
                for (int o = 16; o > 0; o >>= 1) {
                    #pragma unroll
                    for (int e = 0; e < 8; e++)
                        sA[e] += __shfl_xor_sync(FULL, sA[e], o);
                    #pragma unroll
                    for (int e = 0; e < 8; e++)
                        qA[e] += __shfl_xor_sync(FULL, qA[e], o);
                }
                #pragma unroll
                for (int e = 0; e < 8; e++) {
                    const float mean = sA[e] * 0.015625f;
                    const float var  = fmaf(qA[e], 0.015625f, -mean * mean);
                    const float rs   = rsqrtf(var + 1e-5f);
                    float fLo = fmaf((yLo[e] - mean) * rs, fgLo, fbLo);
                    float fHi = fmaf((yHi[e] - mean) * rs, fgHi, fbHi);
                    fLo = fLo > 0.f ? fLo : 0.01f * fLo;
                    fHi = fHi > 0.f ? fHi : 0.01f * fHi;
                    if ((msk >> e) & 1) {
                        out[(size_t)(n0 + e) * 64 + lane] = fLo;
                        out[(size_t)(n0 + e) * 64 + lhi]  = fHi;
                    } else {
                        reinterpret_cast<float2*>(out)[(size_t)(n0 + e) * 32 + lane] = gfvC[e];
                    }
                }
            }
            __syncwarp();   // actw reads done before next iter overwrites
        }

        // rotate pipeline registers
        mC = mN; s0C = s0N;
        #pragma unroll
        for (int e = 0; e < 8; e++) {
            svC[e]  = svN[e];
            gfvC[e] = gfvN[e];
        }
    }
}

// ---------------------------------------------------------------------------
extern "C" void kernel_launch(void* const* d_in, const int* in_sizes, int n_in,
                              void* d_out, int out_size)
{
    const float* gf  = (const float*)d_in[0];
    const float* pos = (const float*)d_in[1];
    const int*   edg = (const int*)  d_in[2];
    const float* wgt = (const float*)d_in[3];
    const float* W1  = (const float*)d_in[4];
    const float* b1  = (const float*)d_in[5];
    const float* W2  = (const float*)d_in[6];
    const float* b2  = (const float*)d_in[7];
    const float* gdg = (const float*)d_in[8];
    const float* gdb = (const float*)d_in[9];
    const float* Wa  = (const float*)d_in[10];
    const float* ba  = (const float*)d_in[11];
    const float* gng = (const float*)d_in[12];
    const float* gnb = (const float*)d_in[13];
    const float* Wf  = (const float*)d_in[14];
    const float* bf  = (const float*)d_in[15];
    const float* gfg = (const float*)d_in[16];
    const float* gfb = (const float*)d_in[17];
    float* out = (float*)d_out;

    const int E = in_sizes[3];
    const int N = in_sizes[0] / 64;

    static const size_t node_smem = (4352 + 8448 + 8192) * sizeof(float);
    cudaFuncSetAttribute(node_kernel, cudaFuncAttributeMaxDynamicSharedMemorySize,
                         (int)node_smem);

    zero_kernel<<<2368, 256>>>(N);
    edge_kernel<<<296, 256>>>(gf, pos, edg, wgt, W1, b1, W2, b2, gdg, gdb, E);
    node_kernel<<<296, 256, node_smem>>>(gf, Wa, ba, gng, gnb, Wf, bf, gfg, gfb, out, N);
}